// round 16
// baseline (speedup 1.0000x reference)
#include <cuda_runtime.h>
#include <cuda_fp16.h>
#include <math.h>
#include <stdint.h>

// Problem constants
#define B_    4
#define S_    2048
#define D_    768
#define H_    12
#define DK_   64
#define F_    3072
#define M_    (B_*S_)        // 8192 rows
#define NQKV_ (3*D_)         // 2304

// ---------------- scratch (static device globals; no allocation) ----------------
__device__ __half g_wqkvT[NQKV_*D_];   // packed+transposed QKV weights [3*H*DK][D] (Wq pre-scaled by 0.125)
__device__ float  g_bqkv[NQKV_];       // packed QKV bias (fp32; bq pre-scaled by 0.125)
__device__ __half g_woT [D_*D_];       // Wo^T  [D][D]
__device__ __half g_w1T [F_*D_];       // W1^T  [F][D]
__device__ __half g_w2T [D_*F_];       // W2^T  [D][F]
__device__ __half g_srch[M_*D_];       // fp16 source
__device__ __half g_x1h [M_*D_];       // fp16 x1
__device__ __half g_qkvh[M_*NQKV_];    // fp16 qkv (q|k|v), q pre-scaled
__device__ __half g_attnh[M_*D_];      // fp16 concat-head attention out
__device__ __half g_ffn1h[M_*F_];      // fp16 relu(ffn1)
__device__ __half g_mhah [2*M_*D_];    // fp16 out-proj K-split partials (2x)
__device__ __half g_ffn2h[2*M_*D_];    // fp16 ffn2 K-split partials (2x)
__device__ float  g_x1  [M_*D_];

// ---------------- helpers ----------------
__device__ __forceinline__ void mma_f16(float* d, const uint32_t* a, const uint32_t* b) {
    asm volatile(
        "mma.sync.aligned.m16n8k16.row.col.f32.f16.f16.f32 "
        "{%0,%1,%2,%3}, {%4,%5,%6,%7}, {%8,%9}, {%0,%1,%2,%3};"
        : "+f"(d[0]), "+f"(d[1]), "+f"(d[2]), "+f"(d[3])
        : "r"(a[0]), "r"(a[1]), "r"(a[2]), "r"(a[3]), "r"(b[0]), "r"(b[1]));
}

__device__ __forceinline__ void ldsm4(uint32_t* r, uint32_t addr) {
    asm volatile("ldmatrix.sync.aligned.m8n8.x4.shared.b16 {%0,%1,%2,%3}, [%4];"
                 : "=r"(r[0]), "=r"(r[1]), "=r"(r[2]), "=r"(r[3]) : "r"(addr));
}

__device__ __forceinline__ void ldsm4t(uint32_t* r, uint32_t addr) {
    asm volatile("ldmatrix.sync.aligned.m8n8.x4.trans.shared.b16 {%0,%1,%2,%3}, [%4];"
                 : "=r"(r[0]), "=r"(r[1]), "=r"(r[2]), "=r"(r[3]) : "r"(addr));
}

__device__ __forceinline__ void cp_async16(uint32_t smem_dst, const void* gmem_src) {
    asm volatile("cp.async.cg.shared.global [%0], [%1], 16;" :: "r"(smem_dst), "l"(gmem_src));
}
#define CP_COMMIT() asm volatile("cp.async.commit_group;")
#define CP_WAIT0()  asm volatile("cp.async.wait_group 0;")
#define CP_WAIT1()  asm volatile("cp.async.wait_group 1;")

__device__ __forceinline__ uint32_t h2u(__half2 h) { return *reinterpret_cast<uint32_t*>(&h); }

__device__ __forceinline__ uint32_t ex2_f16x2(uint32_t x) {
    uint32_t r;
    asm("ex2.approx.f16x2 %0, %1;" : "=r"(r) : "r"(x));
    return r;
}

// ---------------- fused prep kernel: src cvt + bias pack + all weight transposes ----------------
#define PB_CVT   6144
#define PB_BIAS  9
#define PB_WO    576
#define PB_W1    2304
#define PB_W2    2304
#define PB_QKV   1728
#define PB_TOTAL (PB_CVT + PB_BIAS + PB_WO + PB_W1 + PB_W2 + PB_QKV)

__global__ __launch_bounds__(256) void prep_all(
    const float* __restrict__ src,
    const float* __restrict__ Wq, const float* __restrict__ Wk, const float* __restrict__ Wv,
    const float* __restrict__ bq, const float* __restrict__ bk, const float* __restrict__ bv,
    const float* __restrict__ Wo, const float* __restrict__ W1, const float* __restrict__ W2)
{
    int bid = blockIdx.x;
    const int t = threadIdx.x;

    if (bid < PB_CVT) {                     // src fp32 -> fp16
        int i = bid * 256 + t;
        float4 v = *(const float4*)(src + (size_t)i * 4);
        uint2 o;
        o.x = h2u(__floats2half2_rn(v.x, v.y));
        o.y = h2u(__floats2half2_rn(v.z, v.w));
        *(uint2*)(g_srch + (size_t)i * 4) = o;
        return;
    }
    bid -= PB_CVT;
    if (bid < PB_BIAS) {                    // qkv bias pack (bq scaled by 0.125)
        int idx = bid * 256 + t;
        if (idx < NQKV_) {
            int wh = idx / D_, jj = idx % D_;
            const float* bsrc = (wh == 0) ? bq : (wh == 1) ? bk : bv;
            float sc = (wh == 0) ? 0.125f : 1.0f;
            g_bqkv[idx] = bsrc[jj] * sc;
        }
        return;
    }
    bid -= PB_BIAS;

    __shared__ float tile[32][33];
    const int tx = t & 31, ty = t >> 5;

    const float* in; __half* out;
    int C, r0, c0, obase, outLD;
    float wscale = 1.0f;
    if (bid < PB_WO) {
        in = Wo; out = g_woT; C = D_; outLD = D_; obase = 0;
        c0 = (bid % 24) * 32; r0 = (bid / 24) * 32;
    } else if (bid < PB_WO + PB_W1) {
        bid -= PB_WO;
        in = W1; out = g_w1T; C = F_; outLD = D_; obase = 0;
        c0 = (bid % 96) * 32; r0 = (bid / 96) * 32;
    } else if (bid < PB_WO + PB_W1 + PB_W2) {
        bid -= PB_WO + PB_W1;
        in = W2; out = g_w2T; C = D_; outLD = F_; obase = 0;
        c0 = (bid % 24) * 32; r0 = (bid / 24) * 32;
    } else {
        bid -= PB_WO + PB_W1 + PB_W2;
        const int z = bid / 48;
        const int j = bid % 48;
        const int wh = z / H_, h = z % H_;
        in = ((wh == 0) ? Wq : (wh == 1) ? Wk : Wv) + (size_t)h * D_ * DK_;
        out = g_wqkvT; C = DK_; outLD = D_;
        obase = wh * D_ + h * DK_;
        if (wh == 0) wscale = 0.125f;
        c0 = (j % 2) * 32; r0 = (j / 2) * 32;
    }

#pragma unroll
    for (int i = 0; i < 32; i += 8)
        tile[ty + i][tx] = in[(size_t)(r0 + ty + i) * C + c0 + tx];
    __syncthreads();
#pragma unroll
    for (int i = 0; i < 32; i += 8)
        out[(size_t)(obase + c0 + ty + i) * outLD + r0 + tx] =
            __float2half_rn(tile[tx][ty + i] * wscale);
}

// ---------------- FP16 tensor-core GEMM: ldmatrix + cp.async, 3 stages ----------------
// C = A[M,K] @ Bt[N,K]^T (+bias, opt ReLU). CTA 128xBN, 8 warps.
// SPLITK: blockIdx.z picks K-half; writes raw partial (no bias) to Cv + z*M*N (fp16).
#define BMg 128
#define BKg 64
#define STAGES 3
#define A_CHUNKS (BMg*8)

constexpr int gemm_smem_bytes(int BN) { return STAGES * (A_CHUNKS + BN * 8) * 16; }

template<int RELU, int OUTH, int BN, int SPLITK>
__global__ __launch_bounds__(256, (BN == 128) ? 2 : 1) void gemm_f16(
    const __half* __restrict__ A, const __half* __restrict__ Bt,
    const float* __restrict__ bias, void* __restrict__ Cv,
    int M, int N, int K)
{
    constexpr int B_CHUNKS = BN * 8;
    constexpr int STAGE_CHUNKS = A_CHUNKS + B_CHUNKS;
    constexpr int WN = BN / 4;
    constexpr int NT = WN / 8;
    constexpr int NB = WN / 16;

    extern __shared__ uint4 smem4[];
    const uint32_t smem_base = (uint32_t)__cvta_generic_to_shared(smem4);

    const int t    = threadIdx.x;
    const int lane = t & 31;
    const int wid  = t >> 5;
    const int wm   = wid & 1;
    const int wn   = wid >> 1;
    const int rowC = blockIdx.y * BMg;
    const int colC = blockIdx.x * BN;

    const int kLen = SPLITK ? (K >> 1) : K;
    const int kOff = SPLITK ? (blockIdx.z * kLen) : 0;

    float acc[4][NT][4];
#pragma unroll
    for (int i = 0; i < 4; i++)
#pragma unroll
        for (int j = 0; j < NT; j++)
#pragma unroll
            for (int r = 0; r < 4; r++) acc[i][j][r] = 0.f;

    const int ntiles = kLen / BKg;

    auto load_tile = [&](int stage, int kt) {
        const uint32_t sa = smem_base + stage * (STAGE_CHUNKS * 16);
#pragma unroll
        for (int i = 0; i < 4; i++) {
            int lin = i * 256 + t;
            int m = lin >> 3, c = lin & 7;
            uint32_t dst = sa + (uint32_t)(m * 8 + (c ^ (m & 7))) * 16;
            cp_async16(dst, A + (size_t)(rowC + m) * K + kOff + kt * BKg + c * 8);
        }
#pragma unroll
        for (int i = 0; i < B_CHUNKS / 256; i++) {
            int lin = i * 256 + t;
            int n = lin >> 3, c = lin & 7;
            uint32_t dst = sa + (uint32_t)(A_CHUNKS + n * 8 + (c ^ (n & 7))) * 16;
            cp_async16(dst, Bt + (size_t)(colC + n) * K + kOff + kt * BKg + c * 8);
        }
        CP_COMMIT();
    };

    load_tile(0, 0);
    load_tile(1, 1);

    const int lr = lane & 15;
    const int hi = lane >> 4;
    const int x7 = lane & 7;
    uint32_t aRowOff[4], bRowOff[NB];
#pragma unroll
    for (int mt = 0; mt < 4; mt++)
        aRowOff[mt] = (uint32_t)(wm * 64 + mt * 16 + lr) * 128;
#pragma unroll
    for (int nb = 0; nb < NB; nb++)
        bRowOff[nb] = (uint32_t)(A_CHUNKS * 16) + (uint32_t)(wn * WN + nb * 16 + lr) * 128;

    for (int kt = 0; kt < ntiles; kt++) {
        CP_WAIT1();
        __syncthreads();

        const int nxt = kt + STAGES - 1;
        if (nxt < ntiles) load_tile(nxt % STAGES, nxt);
        else              CP_COMMIT();

        const uint32_t sa = smem_base + (kt % STAGES) * (STAGE_CHUNKS * 16);
#pragma unroll
        for (int kk = 0; kk < 4; kk++) {
            const uint32_t cx = (uint32_t)(((2 * kk + hi) ^ x7) * 16);
            uint32_t a[4][4], bfr[NB][4];
#pragma unroll
            for (int mt = 0; mt < 4; mt++)
                ldsm4(a[mt], sa + aRowOff[mt] + cx);
#pragma unroll
            for (int nb = 0; nb < NB; nb++)
                ldsm4(bfr[nb], sa + bRowOff[nb] + cx);
#pragma unroll
            for (int mt = 0; mt < 4; mt++)
#pragma unroll
                for (int nt = 0; nt < NT; nt++) {
                    uint32_t bb[2];
                    bb[0] = bfr[nt >> 1][(nt & 1)];
                    bb[1] = bfr[nt >> 1][2 + (nt & 1)];
                    mma_f16(acc[mt][nt], a[mt], bb);
                }
        }
    }

    // epilogue
    const int g2 = lane >> 2, q2 = lane & 3;
    __half* Cpart = SPLITK ? ((__half*)Cv + (size_t)blockIdx.z * M * N) : (__half*)Cv;
#pragma unroll
    for (int mt = 0; mt < 4; mt++) {
        const int r0 = rowC + wm * 64 + mt * 16 + g2;
#pragma unroll
        for (int nt = 0; nt < NT; nt++) {
            const int c = colC + wn * WN + nt * 8 + 2 * q2;
            float o00 = acc[mt][nt][0], o01 = acc[mt][nt][1];
            float o10 = acc[mt][nt][2], o11 = acc[mt][nt][3];
            if (!SPLITK) {
                const float b0v = bias[c], b1v = bias[c + 1];
                o00 += b0v; o01 += b1v; o10 += b0v; o11 += b1v;
                if (RELU) {
                    o00 = fmaxf(o00, 0.f); o01 = fmaxf(o01, 0.f);
                    o10 = fmaxf(o10, 0.f); o11 = fmaxf(o11, 0.f);
                }
            }
            if (OUTH) {
                *(uint32_t*)(Cpart + (size_t)r0 * N + c)       = h2u(__floats2half2_rn(o00, o01));
                *(uint32_t*)(Cpart + (size_t)(r0 + 8) * N + c) = h2u(__floats2half2_rn(o10, o11));
            } else {
                float* Cf = (float*)Cv;
                *(float2*)(Cf + (size_t)r0 * N + c)       = make_float2(o00, o01);
                *(float2*)(Cf + (size_t)(r0 + 8) * N + c) = make_float2(o10, o11);
            }
        }
    }
}

// ---------------- FP16 mma flash attention (register-P, f16x2 ex2 softmax, 2 CTAs/SM) ----------------
#define AT_BQ 128
#define AT_BK 64
#define ATQ_BYTES (AT_BQ * 64 * 2)
#define ATKV_STAGE (AT_BK * 64 * 2 * 2)
#define ATT_SMEM (ATQ_BYTES + 2 * ATKV_STAGE)

__global__ __launch_bounds__(256, 2) void attn_f16_kernel(
    const __half* __restrict__ qkv, __half* __restrict__ out)
{
    extern __shared__ uint4 smemA[];
    const uint32_t sb = (uint32_t)__cvta_generic_to_shared(smemA);

    const int t    = threadIdx.x;
    const int w    = t >> 5;
    const int lane = t & 31;
    const int g    = lane >> 2;
    const int q    = lane & 3;
    const int lr   = lane & 15;
    const int hi   = lane >> 4;
    const int x7   = lane & 7;
    const int qb = blockIdx.x, h = blockIdx.y, b = blockIdx.z;

    const __half* qg = qkv + (size_t)(b * S_ + qb * AT_BQ) * NQKV_ + h * DK_;

#pragma unroll
    for (int i = 0; i < 4; i++) {
        int lin = i * 256 + t;
        int row = lin >> 3, c = lin & 7;
        uint32_t dst = sb + (uint32_t)(row * 8 + (c ^ (row & 7))) * 16;
        cp_async16(dst, qg + (size_t)row * NQKV_ + c * 8);
    }
    CP_COMMIT();
    CP_WAIT0();
    __syncthreads();

    uint32_t qa[4][4];
    {
        const uint32_t qRowOff = (uint32_t)(w * 16 + lr) * 128;
#pragma unroll
        for (int kb2 = 0; kb2 < 4; kb2++)
            ldsm4(qa[kb2], sb + qRowOff + (uint32_t)(((2 * kb2 + hi) ^ x7) * 16));
    }

    float m0 = -3.0e38f, m1 = -3.0e38f, l0 = 0.f, l1 = 0.f;
    float o[8][4];
#pragma unroll
    for (int nt = 0; nt < 8; nt++)
#pragma unroll
        for (int r = 0; r < 4; r++) o[nt][r] = 0.f;

    const __half* kg = qkv + (size_t)b * S_ * NQKV_ + D_ + h * DK_;

    auto loadKV = [&](int stage, int kb) {
        const uint32_t sbase = sb + ATQ_BYTES + stage * ATKV_STAGE;
        const __half* kr = kg + (size_t)(kb * AT_BK) * NQKV_;
#pragma unroll
        for (int i = 0; i < 2; i++) {
            int lin = i * 256 + t;
            int row = lin >> 3, c = lin & 7;
            uint32_t sw = (uint32_t)(row * 8 + (c ^ (row & 7))) * 16;
            const __half* kp = kr + (size_t)row * NQKV_ + c * 8;
            cp_async16(sbase + sw, kp);
            cp_async16(sbase + (AT_BK * 64 * 2) + sw, kp + D_);
        }
        CP_COMMIT();
    };

    const int NTILES = S_ / AT_BK;
    int buf = 0;
    loadKV(0, 0);

    const float L2E = 1.4426950408889634f;

    for (int kb = 0; kb < NTILES; kb++) {
        const bool more = (kb + 1) < NTILES;
        if (more) loadKV(buf ^ 1, kb + 1);
        if (more) { CP_WAIT1(); } else { CP_WAIT0(); }
        __syncthreads();

        const uint32_t kbase = sb + ATQ_BYTES + buf * ATKV_STAGE;
        const uint32_t vbase = kbase + AT_BK * 64 * 2;

        float s[8][4];
#pragma unroll
        for (int nt = 0; nt < 8; nt++)
#pragma unroll
            for (int r = 0; r < 4; r++) s[nt][r] = 0.f;

#pragma unroll
        for (int nb = 0; nb < 4; nb++) {
            uint32_t kf[4][4];
            const uint32_t kro = (uint32_t)(nb * 16 + lr) * 128;
#pragma unroll
            for (int kb2 = 0; kb2 < 4; kb2++)
                ldsm4(kf[kb2], kbase + kro + (uint32_t)(((2 * kb2 + hi) ^ x7) * 16));
#pragma unroll
            for (int kb2 = 0; kb2 < 4; kb2++) {
                uint32_t b0[2] = { kf[kb2][0], kf[kb2][2] };
                uint32_t b1[2] = { kf[kb2][1], kf[kb2][3] };
                mma_f16(s[2 * nb],     qa[kb2], b0);
                mma_f16(s[2 * nb + 1], qa[kb2], b1);
            }
        }

        float mx0 = -3.0e38f, mx1 = -3.0e38f;
#pragma unroll
        for (int nt = 0; nt < 8; nt++) {
            mx0 = fmaxf(mx0, fmaxf(s[nt][0], s[nt][1]));
            mx1 = fmaxf(mx1, fmaxf(s[nt][2], s[nt][3]));
        }
        mx0 = fmaxf(mx0, __shfl_xor_sync(0xffffffffu, mx0, 1));
        mx0 = fmaxf(mx0, __shfl_xor_sync(0xffffffffu, mx0, 2));
        mx1 = fmaxf(mx1, __shfl_xor_sync(0xffffffffu, mx1, 1));
        mx1 = fmaxf(mx1, __shfl_xor_sync(0xffffffffu, mx1, 2));

        const float mn0 = fmaxf(m0, mx0), mn1 = fmaxf(m1, mx1);
        const float f0 = __expf(m0 - mn0), f1 = __expf(m1 - mn1);
        m0 = mn0; m1 = mn1;

        const float a0 = mn0 * L2E, a1 = mn1 * L2E;
        uint32_t pa[4][4];
        float ls0 = 0.f, ls1 = 0.f;
#pragma unroll
        for (int nt = 0; nt < 8; nt++) {
            float t00 = fmaf(s[nt][0], L2E, -a0);
            float t01 = fmaf(s[nt][1], L2E, -a0);
            float t10 = fmaf(s[nt][2], L2E, -a1);
            float t11 = fmaf(s[nt][3], L2E, -a1);
            uint32_t p0 = ex2_f16x2(h2u(__floats2half2_rn(t00, t01)));
            uint32_t p1 = ex2_f16x2(h2u(__floats2half2_rn(t10, t11)));
            if (nt & 1) { pa[nt >> 1][2] = p0; pa[nt >> 1][3] = p1; }
            else        { pa[nt >> 1][0] = p0; pa[nt >> 1][1] = p1; }
            float2 q0 = __half22float2(*reinterpret_cast<__half2*>(&p0));
            float2 q1 = __half22float2(*reinterpret_cast<__half2*>(&p1));
            ls0 += q0.x + q0.y;
            ls1 += q1.x + q1.y;
        }
        ls0 += __shfl_xor_sync(0xffffffffu, ls0, 1);
        ls0 += __shfl_xor_sync(0xffffffffu, ls0, 2);
        ls1 += __shfl_xor_sync(0xffffffffu, ls1, 1);
        ls1 += __shfl_xor_sync(0xffffffffu, ls1, 2);
        l0 = l0 * f0 + ls0;
        l1 = l1 * f1 + ls1;

#pragma unroll
        for (int nt = 0; nt < 8; nt++) {
            o[nt][0] *= f0; o[nt][1] *= f0;
            o[nt][2] *= f1; o[nt][3] *= f1;
        }

#pragma unroll
        for (int nb2 = 0; nb2 < 4; nb2++) {
            const uint32_t cxv = (uint32_t)(((2 * nb2 + hi) ^ x7) * 16);
#pragma unroll
            for (int kb2 = 0; kb2 < 4; kb2++) {
                uint32_t vf[4];
                ldsm4t(vf, vbase + (uint32_t)(kb2 * 16 + lr) * 128 + cxv);
                uint32_t b0[2] = { vf[0], vf[1] };
                uint32_t b1[2] = { vf[2], vf[3] };
                mma_f16(o[2 * nb2],     pa[kb2], b0);
                mma_f16(o[2 * nb2 + 1], pa[kb2], b1);
            }
        }

        __syncthreads();
        buf ^= 1;
    }

    const float i0 = 1.0f / l0, i1 = 1.0f / l1;
    __half* op = out + (size_t)(b * S_ + qb * AT_BQ + w * 16) * D_ + h * DK_;
#pragma unroll
    for (int nt = 0; nt < 8; nt++) {
        const int c = nt * 8 + 2 * q;
        *(uint32_t*)(op + (size_t)g * D_ + c) =
            h2u(__floats2half2_rn(o[nt][0] * i0, o[nt][1] * i0));
        *(uint32_t*)(op + (size_t)(g + 8) * D_ + c) =
            h2u(__floats2half2_rn(o[nt][2] * i1, o[nt][3] * i1));
    }
}

// ---------------- fused residual-add + LayerNorm over split-K partials ----------------
// v = A(fp32) + P0(fp16) + P1(fp16) + bvec; then LN with gamma/beta.
template<int DUAL>
__global__ __launch_bounds__(256) void add_ln_kernel(
    const float* __restrict__ A, const __half* __restrict__ P0, const __half* __restrict__ P1,
    const float* __restrict__ bvec,
    const float* __restrict__ gamma, const float* __restrict__ beta,
    float* __restrict__ out, __half* __restrict__ outh)
{
    const int w    = threadIdx.x >> 5;
    const int lane = threadIdx.x & 31;
    const int row  = blockIdx.x * 8 + w;

    const float*  pa = A  + (size_t)row * D_;
    const __half* p0 = P0 + (size_t)row * D_;
    const __half* p1 = P1 + (size_t)row * D_;

    float4 v[6];
    float s = 0.f;
#pragma unroll
    for (int i = 0; i < 6; i++) {
        const int off = (i * 32 + lane) * 4;
        float4 a4 = *(const float4*)(pa + off);
        float4 b4 = *(const float4*)(bvec + off);
        uint2 h0 = *(const uint2*)(p0 + off);
        uint2 h1 = *(const uint2*)(p1 + off);
        float2 c0 = __half22float2(*reinterpret_cast<__half2*>(&h0.x));
        float2 c1 = __half22float2(*reinterpret_cast<__half2*>(&h0.y));
        float2 d0 = __half22float2(*reinterpret_cast<__half2*>(&h1.x));
        float2 d1 = __half22float2(*reinterpret_cast<__half2*>(&h1.y));
        v[i].x = a4.x + b4.x + c0.x + d0.x;
        v[i].y = a4.y + b4.y + c0.y + d0.y;
        v[i].z = a4.z + b4.z + c1.x + d1.x;
        v[i].w = a4.w + b4.w + c1.y + d1.y;
        s += v[i].x + v[i].y + v[i].z + v[i].w;
    }
#pragma unroll
    for (int mk = 16; mk; mk >>= 1) s += __shfl_xor_sync(0xffffffffu, s, mk);
    const float mean = s * (1.0f / D_);

    float qv = 0.f;
#pragma unroll
    for (int i = 0; i < 6; i++) {
        v[i].x -= mean; v[i].y -= mean; v[i].z -= mean; v[i].w -= mean;
        qv += v[i].x * v[i].x + v[i].y * v[i].y + v[i].z * v[i].z + v[i].w * v[i].w;
    }
#pragma unroll
    for (int mk = 16; mk; mk >>= 1) qv += __shfl_xor_sync(0xffffffffu, qv, mk);
    const float rstd = rsqrtf(qv * (1.0f / D_) + 1e-5f);

    float* po = out + (size_t)row * D_;
    __half* ph = DUAL ? (outh + (size_t)row * D_) : nullptr;
#pragma unroll
    for (int i = 0; i < 6; i++) {
        const int off = (i * 32 + lane) * 4;
        float4 g4 = *(const float4*)(gamma + off);
        float4 e4 = *(const float4*)(beta + off);
        float4 r;
        r.x = v[i].x * rstd * g4.x + e4.x;
        r.y = v[i].y * rstd * g4.y + e4.y;
        r.z = v[i].z * rstd * g4.z + e4.z;
        r.w = v[i].w * rstd * g4.w + e4.w;
        *(float4*)(po + off) = r;
        if (DUAL) {
            uint2 hh;
            hh.x = h2u(__floats2half2_rn(r.x, r.y));
            hh.y = h2u(__floats2half2_rn(r.z, r.w));
            *(uint2*)(ph + off) = hh;
        }
    }
}

// ---------------- launch ----------------
extern "C" void kernel_launch(void* const* d_in, const int* in_sizes, int n_in,
                              void* d_out, int out_size)
{
    const float* src = (const float*)d_in[0];
    const float* Wq  = (const float*)d_in[1];
    const float* bq  = (const float*)d_in[2];
    const float* Wk  = (const float*)d_in[3];
    const float* bk  = (const float*)d_in[4];
    const float* Wv  = (const float*)d_in[5];
    const float* bv  = (const float*)d_in[6];
    const float* Wo  = (const float*)d_in[7];
    const float* bo  = (const float*)d_in[8];
    const float* g1  = (const float*)d_in[9];
    const float* be1 = (const float*)d_in[10];
    const float* W1  = (const float*)d_in[11];
    const float* bf1 = (const float*)d_in[12];
    const float* W2  = (const float*)d_in[13];
    const float* bf2 = (const float*)d_in[14];
    const float* g2  = (const float*)d_in[15];
    const float* be2 = (const float*)d_in[16];
    float* out = (float*)d_out;

    __half *wqkvT, *woT, *w1T, *w2T, *srch, *x1h, *qkvh, *attnh, *ffn1h, *mhah, *ffn2h;
    float *bqkv, *x1;
    cudaGetSymbolAddress((void**)&wqkvT, g_wqkvT);
    cudaGetSymbolAddress((void**)&bqkv,  g_bqkv);
    cudaGetSymbolAddress((void**)&woT,   g_woT);
    cudaGetSymbolAddress((void**)&w1T,   g_w1T);
    cudaGetSymbolAddress((void**)&w2T,   g_w2T);
    cudaGetSymbolAddress((void**)&srch,  g_srch);
    cudaGetSymbolAddress((void**)&x1h,   g_x1h);
    cudaGetSymbolAddress((void**)&qkvh,  g_qkvh);
    cudaGetSymbolAddress((void**)&attnh, g_attnh);
    cudaGetSymbolAddress((void**)&ffn1h, g_ffn1h);
    cudaGetSymbolAddress((void**)&mhah,  g_mhah);
    cudaGetSymbolAddress((void**)&ffn2h, g_ffn2h);
    cudaGetSymbolAddress((void**)&x1,    g_x1);

    const int smem256 = gemm_smem_bytes(256);   // 147456
    const int smem128 = gemm_smem_bytes(128);   // 98304
    cudaFuncSetAttribute((const void*)gemm_f16<0,1,256,0>, cudaFuncAttributeMaxDynamicSharedMemorySize, smem256);
    cudaFuncSetAttribute((const void*)gemm_f16<1,1,256,0>, cudaFuncAttributeMaxDynamicSharedMemorySize, smem256);
    cudaFuncSetAttribute((const void*)gemm_f16<0,1,128,1>, cudaFuncAttributeMaxDynamicSharedMemorySize, smem128);
    cudaFuncSetAttribute((const void*)attn_f16_kernel, cudaFuncAttributeMaxDynamicSharedMemorySize, ATT_SMEM);

    // 0) fused operand prep
    prep_all<<<PB_TOTAL, 256>>>(src, Wq, Wk, Wv, bq, bk, bv, Wo, W1, W2);

    // 1) QKV projection -> fp16 qkv   (grid 9x64 = 576)
    gemm_f16<0,1,256,0><<<dim3(NQKV_ / 256, M_ / BMg), 256, smem256>>>(srch, wqkvT, bqkv, qkvh, M_, NQKV_, D_);

    // 2) fused attention -> fp16 attn  (2 CTAs/SM)
    attn_f16_kernel<<<dim3(S_ / AT_BQ, H_, B_), 256, ATT_SMEM>>>(qkvh, attnh);

    // 3) output projection, split-K=2 -> fp16 partials (grid 6x64x2 = 768, 2 CTAs/SM)
    gemm_f16<0,1,128,1><<<dim3(D_ / 128, M_ / BMg, 2), 256, smem128>>>(attnh, woT, nullptr, mhah, M_, D_, D_);

    // 4) x1 = LN(src + mha0 + mha1 + bo), dual fp32 + fp16
    add_ln_kernel<1><<<M_ / 8, 256>>>(src, mhah, mhah + (size_t)M_ * D_, bo, g1, be1, x1, x1h);

    // 5) FFN1 (+ReLU) -> fp16 ffn1  (grid 12x64 = 768)
    gemm_f16<1,1,256,0><<<dim3(F_ / 256, M_ / BMg), 256, smem256>>>(x1h, w1T, bf1, ffn1h, M_, F_, D_);

    // 6) FFN2, split-K=2 -> fp16 partials (grid 6x64x2 = 768, 2 CTAs/SM)
    gemm_f16<0,1,128,1><<<dim3(D_ / 128, M_ / BMg, 2), 256, smem128>>>(ffn1h, w2T, nullptr, ffn2h, M_, D_, F_);

    // 7) out = LN(x1 + ffn2_0 + ffn2_1 + bf2)
    add_ln_kernel<0><<<M_ / 8, 256>>>(x1, ffn2h, ffn2h + (size_t)M_ * D_, bf2, g2, be2, out, nullptr);
}